// round 1
// baseline (speedup 1.0000x reference)
#include <cuda_runtime.h>
#include <cuda_bf16.h>
#include <math.h>

// Problem shape (fixed by reference setup_inputs)
#define BATCH 2
#define SEQ   2048
#define DIM   1024
#define HEADS 16
#define DH    64            // DIM / HEADS
#define MROWS (BATCH*SEQ)   // 4096

// ---------------- scratch (static device memory; no allocs allowed) --------
__device__ float g_Q[MROWS * DIM];
__device__ float g_K[MROWS * DIM];
__device__ float g_V[MROWS * DIM];
__device__ float g_CTX[MROWS * DIM];

// ---------------- fp32 SGEMM: C[M,N] = A[M,K] @ B[K,N] (+bias) -------------
// BM=128 BN=128 BK=8, 256 threads, 8x8 micro-tile per thread.
#define BM 128
#define BN 128
#define BK 8
#define TM 8
#define TN 8

__global__ __launch_bounds__(256) void sgemm_kernel(
    const float* __restrict__ A, const float* __restrict__ B,
    const float* __restrict__ bias, float* __restrict__ C,
    int M, int N, int K)
{
    __shared__ float As[BK][BM];      // transposed A tile
    __shared__ float Bs[BK][BN];

    const int tid  = threadIdx.x;
    const int brow = blockIdx.y;
    const int bcol = blockIdx.x;

    const int tcol = tid % (BN / TN); // 0..15
    const int trow = tid / (BN / TN); // 0..15

    // global load mapping
    const int a_row = tid >> 1;          // 0..127
    const int a_col = (tid & 1) * 4;     // 0 or 4
    const int b_row = tid >> 5;          // 0..7
    const int b_col = (tid & 31) * 4;    // 0..124

    const float* Ab = A + (size_t)(brow * BM) * K;
    const float* Bb = B + bcol * BN;

    float acc[TM][TN];
    #pragma unroll
    for (int i = 0; i < TM; i++)
        #pragma unroll
        for (int j = 0; j < TN; j++) acc[i][j] = 0.f;

    float ar[TM], br[TN];

    for (int k0 = 0; k0 < K; k0 += BK) {
        float4 av = *(const float4*)(Ab + (size_t)a_row * K + k0 + a_col);
        As[a_col + 0][a_row] = av.x;
        As[a_col + 1][a_row] = av.y;
        As[a_col + 2][a_row] = av.z;
        As[a_col + 3][a_row] = av.w;

        float4 bv = *(const float4*)(Bb + (size_t)(k0 + b_row) * N + b_col);
        *(float4*)(&Bs[b_row][b_col]) = bv;

        __syncthreads();

        #pragma unroll
        for (int kk = 0; kk < BK; kk++) {
            #pragma unroll
            for (int i = 0; i < TM; i++) ar[i] = As[kk][trow * TM + i];
            #pragma unroll
            for (int j = 0; j < TN; j++) br[j] = Bs[kk][tcol * TN + j];
            #pragma unroll
            for (int i = 0; i < TM; i++)
                #pragma unroll
                for (int j = 0; j < TN; j++)
                    acc[i][j] += ar[i] * br[j];
        }
        __syncthreads();
    }

    #pragma unroll
    for (int i = 0; i < TM; i++) {
        const int row = brow * BM + trow * TM + i;
        float* Crow = C + (size_t)row * N + bcol * BN + tcol * TN;
        #pragma unroll
        for (int j = 0; j < TN; j += 4) {
            float4 v;
            v.x = acc[i][j + 0];
            v.y = acc[i][j + 1];
            v.z = acc[i][j + 2];
            v.w = acc[i][j + 3];
            if (bias) {
                const float* bp = bias + bcol * BN + tcol * TN + j;
                v.x += bp[0]; v.y += bp[1]; v.z += bp[2]; v.w += bp[3];
            }
            *(float4*)(Crow + j) = v;
        }
    }
}

// ---------------- causal flash attention (fp32) -----------------------------
// grid: (SEQ/BR, HEADS, BATCH), block: BR threads, 1 query row per thread.
#define BR 64
#define BC 64

__global__ __launch_bounds__(BR) void flash_kernel(
    const float* __restrict__ Q, const float* __restrict__ K,
    const float* __restrict__ V, float* __restrict__ O)
{
    const int qb = blockIdx.x;
    const int h  = blockIdx.y;
    const int b  = blockIdx.z;
    const int t  = threadIdx.x;          // query row within tile
    const int qrow = qb * BR + t;

    __shared__ float Ks[BC][DH];
    __shared__ float Vs[BC][DH];

    const float* qptr = Q + ((size_t)(b * SEQ + qrow)) * DIM + h * DH;

    float q[DH], o[DH];
    #pragma unroll
    for (int d = 0; d < DH; d++) { q[d] = qptr[d]; o[d] = 0.f; }

    float m = -1e30f, l = 0.f;
    const float scale = 0.125f;          // 1/sqrt(64)

    const int nkb = qb + 1;              // causal: key blocks 0..qb
    for (int kb = 0; kb < nkb; kb++) {
        const float* kptr = K + ((size_t)(b * SEQ + kb * BC + t)) * DIM + h * DH;
        const float* vptr = V + ((size_t)(b * SEQ + kb * BC + t)) * DIM + h * DH;
        __syncthreads();
        #pragma unroll
        for (int d = 0; d < DH; d += 4) {
            *(float4*)&Ks[t][d] = *(const float4*)(kptr + d);
            *(float4*)&Vs[t][d] = *(const float4*)(vptr + d);
        }
        __syncthreads();

        const int jlim = (kb == qb) ? (t + 1) : BC;
        for (int j = 0; j < jlim; j++) {
            // dot(q, K_j) with 4 partial accumulators for ILP
            float s0 = 0.f, s1 = 0.f, s2 = 0.f, s3 = 0.f;
            #pragma unroll
            for (int d = 0; d < DH; d += 4) {
                s0 += q[d + 0] * Ks[j][d + 0];
                s1 += q[d + 1] * Ks[j][d + 1];
                s2 += q[d + 2] * Ks[j][d + 2];
                s3 += q[d + 3] * Ks[j][d + 3];
            }
            float s = ((s0 + s1) + (s2 + s3)) * scale;

            float mnew = fmaxf(m, s);
            float corr = __expf(m - mnew);
            float p    = __expf(s - mnew);
            l = l * corr + p;
            #pragma unroll
            for (int d = 0; d < DH; d++)
                o[d] = o[d] * corr + p * Vs[j][d];
            m = mnew;
        }
    }

    const float inv = 1.f / l;
    float* optr = O + ((size_t)(b * SEQ + qrow)) * DIM + h * DH;
    #pragma unroll
    for (int d = 0; d < DH; d += 4) {
        float4 v;
        v.x = o[d + 0] * inv;
        v.y = o[d + 1] * inv;
        v.z = o[d + 2] * inv;
        v.w = o[d + 3] * inv;
        *(float4*)(optr + d) = v;
    }
}

// ---------------- launch -----------------------------------------------------
extern "C" void kernel_launch(void* const* d_in, const int* in_sizes, int n_in,
                              void* d_out, int out_size)
{
    const float* x  = (const float*)d_in[0];
    const float* Wq = (const float*)d_in[1];
    const float* Wk = (const float*)d_in[2];
    const float* Wv = (const float*)d_in[3];
    const float* Wo = (const float*)d_in[4];
    const float* bo = (const float*)d_in[5];
    float* out = (float*)d_out;

    float *Qp, *Kp, *Vp, *Cp;
    cudaGetSymbolAddress((void**)&Qp, g_Q);
    cudaGetSymbolAddress((void**)&Kp, g_K);
    cudaGetSymbolAddress((void**)&Vp, g_V);
    cudaGetSymbolAddress((void**)&Cp, g_CTX);

    dim3 gemm_grid(DIM / BN, MROWS / BM);   // (8, 32)
    dim3 gemm_block(256);

    // QKV projections (layout stays [B,S,H,Dh] == [MROWS, DIM])
    sgemm_kernel<<<gemm_grid, gemm_block>>>(x, Wq, nullptr, Qp, MROWS, DIM, DIM);
    sgemm_kernel<<<gemm_grid, gemm_block>>>(x, Wk, nullptr, Kp, MROWS, DIM, DIM);
    sgemm_kernel<<<gemm_grid, gemm_block>>>(x, Wv, nullptr, Vp, MROWS, DIM, DIM);

    // causal attention
    dim3 fa_grid(SEQ / BR, HEADS, BATCH);   // (32, 16, 2)
    flash_kernel<<<fa_grid, BR>>>(Qp, Kp, Vp, Cp);

    // output projection + bias
    sgemm_kernel<<<gemm_grid, gemm_block>>>(Cp, Wo, bo, out, MROWS, DIM, DIM);
}

// round 2
// speedup vs baseline: 1.2096x; 1.2096x over previous
#include <cuda_runtime.h>
#include <cuda_bf16.h>
#include <math.h>

// Problem shape (fixed by reference setup_inputs)
#define BATCH 2
#define SEQ   2048
#define DIM   1024
#define HEADS 16
#define DH    64            // DIM / HEADS
#define MROWS (BATCH*SEQ)   // 4096

// ---------------- scratch (static device memory; no allocs allowed) --------
__device__ float g_Q[MROWS * DIM];
__device__ float g_K[MROWS * DIM];
__device__ float g_V[MROWS * DIM];
__device__ float g_CTX[MROWS * DIM];

// ---------------- packed f32x2 helpers --------------------------------------
__device__ __forceinline__ unsigned long long pack2(float a, float b) {
    unsigned long long r;
    asm("mov.b64 %0, {%1,%2};" : "=l"(r) : "f"(a), "f"(b));
    return r;
}
__device__ __forceinline__ void unpack2(unsigned long long v, float& a, float& b) {
    asm("mov.b64 {%0,%1}, %2;" : "=f"(a), "=f"(b) : "l"(v));
}
__device__ __forceinline__ unsigned long long fma2(unsigned long long a,
                                                   unsigned long long b,
                                                   unsigned long long c) {
    unsigned long long d;
    asm("fma.rn.f32x2 %0, %1, %2, %3;" : "=l"(d) : "l"(a), "l"(b), "l"(c));
    return d;
}
__device__ __forceinline__ unsigned long long mul2(unsigned long long a,
                                                   unsigned long long b) {
    unsigned long long d;
    asm("mul.rn.f32x2 %0, %1, %2;" : "=l"(d) : "l"(a), "l"(b));
    return d;
}

// ---------------- fp32 SGEMM: C[M,N] = A[M,K] @ B[K,N] (+bias) -------------
// BM=128 BN=128 BK=8, 256 threads, 8x8 micro-tile, f32x2 packed FMA,
// double-buffered shared memory.
#define BM 128
#define BN 128
#define BK 8
#define TM 8
#define TN 8

__global__ __launch_bounds__(256) void sgemm_kernel(
    const float* __restrict__ A, const float* __restrict__ B,
    const float* __restrict__ bias, float* __restrict__ C,
    int M, int N, int K)
{
    __shared__ float As[2][BK][BM];      // transposed A tile
    __shared__ float Bs[2][BK][BN];

    const int tid  = threadIdx.x;
    const int brow = blockIdx.y;
    const int bcol = blockIdx.x;

    const int tcol = tid % (BN / TN); // 0..15
    const int trow = tid / (BN / TN); // 0..15

    const int a_row = tid >> 1;          // 0..127
    const int a_col = (tid & 1) * 4;     // 0 or 4
    const int b_row = tid >> 5;          // 0..7
    const int b_col = (tid & 31) * 4;    // 0..124

    const float* Ab = A + (size_t)(brow * BM) * K;
    const float* Bb = B + bcol * BN;

    unsigned long long acc2[TM][TN / 2];
    #pragma unroll
    for (int i = 0; i < TM; i++)
        #pragma unroll
        for (int j = 0; j < TN / 2; j++) acc2[i][j] = 0ull;

    // prologue: stage k0 = 0
    {
        float4 av = *(const float4*)(Ab + (size_t)a_row * K + a_col);
        As[0][a_col + 0][a_row] = av.x;
        As[0][a_col + 1][a_row] = av.y;
        As[0][a_col + 2][a_row] = av.z;
        As[0][a_col + 3][a_row] = av.w;
        float4 bv = *(const float4*)(Bb + (size_t)b_row * N + b_col);
        *(float4*)(&Bs[0][b_row][b_col]) = bv;
    }
    __syncthreads();

    int buf = 0;
    for (int k0 = 0; k0 < K; k0 += BK) {
        const bool more = (k0 + BK) < K;
        float4 avn, bvn;
        if (more) {
            avn = *(const float4*)(Ab + (size_t)a_row * K + (k0 + BK) + a_col);
            bvn = *(const float4*)(Bb + (size_t)(k0 + BK + b_row) * N + b_col);
        }

        #pragma unroll
        for (int kk = 0; kk < BK; kk++) {
            float4 a0 = *(const float4*)(&As[buf][kk][trow * TM]);
            float4 a1 = *(const float4*)(&As[buf][kk][trow * TM + 4]);
            ulonglong2 b0 = *(const ulonglong2*)(&Bs[buf][kk][tcol * TN]);
            ulonglong2 b1 = *(const ulonglong2*)(&Bs[buf][kk][tcol * TN + 4]);
            unsigned long long br2[4] = { b0.x, b0.y, b1.x, b1.y };
            unsigned long long ar2[8];
            ar2[0] = pack2(a0.x, a0.x); ar2[1] = pack2(a0.y, a0.y);
            ar2[2] = pack2(a0.z, a0.z); ar2[3] = pack2(a0.w, a0.w);
            ar2[4] = pack2(a1.x, a1.x); ar2[5] = pack2(a1.y, a1.y);
            ar2[6] = pack2(a1.z, a1.z); ar2[7] = pack2(a1.w, a1.w);
            #pragma unroll
            for (int i = 0; i < TM; i++)
                #pragma unroll
                for (int jp = 0; jp < TN / 2; jp++)
                    acc2[i][jp] = fma2(ar2[i], br2[jp], acc2[i][jp]);
        }

        if (more) {
            const int nxt = buf ^ 1;
            As[nxt][a_col + 0][a_row] = avn.x;
            As[nxt][a_col + 1][a_row] = avn.y;
            As[nxt][a_col + 2][a_row] = avn.z;
            As[nxt][a_col + 3][a_row] = avn.w;
            *(float4*)(&Bs[nxt][b_row][b_col]) = bvn;
        }
        __syncthreads();
        buf ^= 1;
    }

    #pragma unroll
    for (int i = 0; i < TM; i++) {
        const int row = brow * BM + trow * TM + i;
        float* Crow = C + (size_t)row * N + bcol * BN + tcol * TN;
        float cv[8];
        #pragma unroll
        for (int jp = 0; jp < TN / 2; jp++)
            unpack2(acc2[i][jp], cv[2 * jp], cv[2 * jp + 1]);
        if (bias) {
            const float* bp = bias + bcol * BN + tcol * TN;
            #pragma unroll
            for (int j = 0; j < TN; j++) cv[j] += bp[j];
        }
        float4 v0 = { cv[0], cv[1], cv[2], cv[3] };
        float4 v1 = { cv[4], cv[5], cv[6], cv[7] };
        *(float4*)(Crow)     = v0;
        *(float4*)(Crow + 4) = v1;
    }
}

// ---------------- causal flash attention (fp32, tiled 2-GEMM) ---------------
// grid: (SEQ/64, HEADS, BATCH), block: 128 threads (4 warps).
// Each thread owns a 4(row) x 8(col) tile of the 64x64 score / output tile.
// Shared: Qt [DH][64] (transposed, pre-scaled), KtPs union ([DH][68] as K^T,
// [64][68] as P), Vs [64][DH]. All inner FMAs are packed f32x2.

#define FBR 64
#define FBC 64
#define FLASH_SMEM ((64*64 + 68*64 + 64*64) * 4)   // 50176 bytes

__global__ __launch_bounds__(128) void flash2_kernel(
    const float* __restrict__ Q, const float* __restrict__ K,
    const float* __restrict__ V, float* __restrict__ O)
{
    extern __shared__ float sm[];
    float* Qt   = sm;                 // [DH][64], stride 64
    float* KtPs = sm + 64 * DH;       // Kt: [DH][68] / Ps: [64][68]
    float* Vs   = KtPs + 68 * 64;     // [64][DH], stride 64

    const int tid  = threadIdx.x;
    const int qb   = gridDim.x - 1 - blockIdx.x;   // big blocks first
    const int h    = blockIdx.y;
    const int b    = blockIdx.z;
    const int tcol = tid & 7;          // 0..7
    const int trow = tid >> 3;         // 0..15
    const int r0   = trow * 4;
    const int c0   = tcol * 8;

    const float qscale = 0.125f * 1.4426950408889634f;   // 1/sqrt(64) * log2(e)

    // load Q tile, transposed + pre-scaled (scores end up in log2 domain)
    const float* Qg = Q + ((size_t)(b * SEQ + qb * FBR)) * DIM + h * DH;
    #pragma unroll
    for (int it = 0; it < 8; it++) {
        int lin = it * 128 + tid;          // 0..1023
        int row = lin & 63;
        int dh  = (lin >> 6) << 2;         // 0,4,...,60
        float4 v = *(const float4*)(Qg + (size_t)row * DIM + dh);
        Qt[(dh + 0) * 64 + row] = v.x * qscale;
        Qt[(dh + 1) * 64 + row] = v.y * qscale;
        Qt[(dh + 2) * 64 + row] = v.z * qscale;
        Qt[(dh + 3) * 64 + row] = v.w * qscale;
    }

    unsigned long long o2[4][4];
    float m[4], l[4];
    #pragma unroll
    for (int i = 0; i < 4; i++) {
        m[i] = -1e30f; l[i] = 0.f;
        #pragma unroll
        for (int jp = 0; jp < 4; jp++) o2[i][jp] = 0ull;
    }

    for (int kb = 0; kb <= qb; kb++) {
        const float* Kg = K + ((size_t)(b * SEQ + kb * FBC)) * DIM + h * DH;
        const float* Vg = V + ((size_t)(b * SEQ + kb * FBC)) * DIM + h * DH;

        __syncthreads();   // prior-tile Ps/Vs readers done before overwrite
        #pragma unroll
        for (int it = 0; it < 8; it++) {
            int lin = it * 128 + tid;
            int row = lin & 63;
            int dh  = (lin >> 6) << 2;
            float4 kv = *(const float4*)(Kg + (size_t)row * DIM + dh);
            KtPs[(dh + 0) * 68 + row] = kv.x;
            KtPs[(dh + 1) * 68 + row] = kv.y;
            KtPs[(dh + 2) * 68 + row] = kv.z;
            KtPs[(dh + 3) * 68 + row] = kv.w;
            *(float4*)(&Vs[row * 64 + dh]) =
                *(const float4*)(Vg + (size_t)row * DIM + dh);
        }
        __syncthreads();

        // ---- S = Q K^T (log2-scaled) ----
        unsigned long long s2[4][4];
        #pragma unroll
        for (int i = 0; i < 4; i++)
            #pragma unroll
            for (int jp = 0; jp < 4; jp++) s2[i][jp] = 0ull;

        #pragma unroll 8
        for (int dh = 0; dh < DH; dh++) {
            float4 aq = *(const float4*)(&Qt[dh * 64 + r0]);
            ulonglong2 kv0 = *(const ulonglong2*)(&KtPs[dh * 68 + c0]);
            ulonglong2 kv1 = *(const ulonglong2*)(&KtPs[dh * 68 + c0 + 4]);
            unsigned long long br2[4] = { kv0.x, kv0.y, kv1.x, kv1.y };
            unsigned long long ar2[4];
            ar2[0] = pack2(aq.x, aq.x);
            ar2[1] = pack2(aq.y, aq.y);
            ar2[2] = pack2(aq.z, aq.z);
            ar2[3] = pack2(aq.w, aq.w);
            #pragma unroll
            for (int i = 0; i < 4; i++)
                #pragma unroll
                for (int jp = 0; jp < 4; jp++)
                    s2[i][jp] = fma2(ar2[i], br2[jp], s2[i][jp]);
        }
        __syncthreads();   // all Kt reads done before Ps overwrites the region

        // ---- online softmax (registers) + stage P into shared ----
        const bool diag = (kb == qb);
        #pragma unroll
        for (int i = 0; i < 4; i++) {
            float sv[8];
            #pragma unroll
            for (int jp = 0; jp < 4; jp++)
                unpack2(s2[i][jp], sv[2 * jp], sv[2 * jp + 1]);
            if (diag) {
                #pragma unroll
                for (int j = 0; j < 8; j++)
                    if (c0 + j > r0 + i) sv[j] = -1e30f;
            }
            float mx = sv[0];
            #pragma unroll
            for (int j = 1; j < 8; j++) mx = fmaxf(mx, sv[j]);
            mx = fmaxf(mx, __shfl_xor_sync(0xffffffffu, mx, 1));
            mx = fmaxf(mx, __shfl_xor_sync(0xffffffffu, mx, 2));
            mx = fmaxf(mx, __shfl_xor_sync(0xffffffffu, mx, 4));

            float mn   = fmaxf(m[i], mx);
            float corr = exp2f(m[i] - mn);
            m[i] = mn;

            float rs = 0.f;
            #pragma unroll
            for (int j = 0; j < 8; j++) { sv[j] = exp2f(sv[j] - mn); rs += sv[j]; }
            rs += __shfl_xor_sync(0xffffffffu, rs, 1);
            rs += __shfl_xor_sync(0xffffffffu, rs, 2);
            rs += __shfl_xor_sync(0xffffffffu, rs, 4);
            l[i] = l[i] * corr + rs;

            unsigned long long c2 = pack2(corr, corr);
            #pragma unroll
            for (int jp = 0; jp < 4; jp++) o2[i][jp] = mul2(o2[i][jp], c2);

            float4 p0 = { sv[0], sv[1], sv[2], sv[3] };
            float4 p1 = { sv[4], sv[5], sv[6], sv[7] };
            *(float4*)(&KtPs[(r0 + i) * 68 + c0])     = p0;
            *(float4*)(&KtPs[(r0 + i) * 68 + c0 + 4]) = p1;
        }
        __syncthreads();

        // ---- O += P V ----
        #pragma unroll 8
        for (int k = 0; k < FBC; k++) {
            unsigned long long a2[4];
            #pragma unroll
            for (int i = 0; i < 4; i++) {
                float av = KtPs[(r0 + i) * 68 + k];
                a2[i] = pack2(av, av);
            }
            ulonglong2 v0 = *(const ulonglong2*)(&Vs[k * 64 + c0]);
            ulonglong2 v1 = *(const ulonglong2*)(&Vs[k * 64 + c0 + 4]);
            unsigned long long br2[4] = { v0.x, v0.y, v1.x, v1.y };
            #pragma unroll
            for (int i = 0; i < 4; i++)
                #pragma unroll
                for (int jp = 0; jp < 4; jp++)
                    o2[i][jp] = fma2(a2[i], br2[jp], o2[i][jp]);
        }
    }

    // ---- normalize + store ----
    float* Og = O + ((size_t)(b * SEQ + qb * FBR)) * DIM + h * DH;
    #pragma unroll
    for (int i = 0; i < 4; i++) {
        const float inv = 1.0f / l[i];
        float ov[8];
        #pragma unroll
        for (int jp = 0; jp < 4; jp++)
            unpack2(o2[i][jp], ov[2 * jp], ov[2 * jp + 1]);
        #pragma unroll
        for (int j = 0; j < 8; j++) ov[j] *= inv;
        float4 v0 = { ov[0], ov[1], ov[2], ov[3] };
        float4 v1 = { ov[4], ov[5], ov[6], ov[7] };
        *(float4*)(Og + (size_t)(r0 + i) * DIM + c0)     = v0;
        *(float4*)(Og + (size_t)(r0 + i) * DIM + c0 + 4) = v1;
    }
}

// ---------------- launch -----------------------------------------------------
extern "C" void kernel_launch(void* const* d_in, const int* in_sizes, int n_in,
                              void* d_out, int out_size)
{
    const float* x  = (const float*)d_in[0];
    const float* Wq = (const float*)d_in[1];
    const float* Wk = (const float*)d_in[2];
    const float* Wv = (const float*)d_in[3];
    const float* Wo = (const float*)d_in[4];
    const float* bo = (const float*)d_in[5];
    float* out = (float*)d_out;

    float *Qp, *Kp, *Vp, *Cp;
    cudaGetSymbolAddress((void**)&Qp, g_Q);
    cudaGetSymbolAddress((void**)&Kp, g_K);
    cudaGetSymbolAddress((void**)&Vp, g_V);
    cudaGetSymbolAddress((void**)&Cp, g_CTX);

    cudaFuncSetAttribute(flash2_kernel,
                         cudaFuncAttributeMaxDynamicSharedMemorySize, FLASH_SMEM);

    dim3 gemm_grid(DIM / BN, MROWS / BM);   // (8, 32)
    dim3 gemm_block(256);

    // QKV projections (layout stays [B,S,H,Dh] == [MROWS, DIM])
    sgemm_kernel<<<gemm_grid, gemm_block>>>(x, Wq, nullptr, Qp, MROWS, DIM, DIM);
    sgemm_kernel<<<gemm_grid, gemm_block>>>(x, Wk, nullptr, Kp, MROWS, DIM, DIM);
    sgemm_kernel<<<gemm_grid, gemm_block>>>(x, Wv, nullptr, Vp, MROWS, DIM, DIM);

    // causal attention
    dim3 fa_grid(SEQ / FBR, HEADS, BATCH);  // (32, 16, 2)
    flash2_kernel<<<fa_grid, 128, FLASH_SMEM>>>(Qp, Kp, Vp, Cp);

    // output projection + bias
    sgemm_kernel<<<gemm_grid, gemm_block>>>(Cp, Wo, bo, out, MROWS, DIM, DIM);
}

// round 5
// speedup vs baseline: 1.6189x; 1.3384x over previous
#include <cuda_runtime.h>
#include <cuda_bf16.h>
#include <stdint.h>
#include <math.h>

// Problem shape (fixed by reference setup_inputs)
#define BATCH 2
#define SEQ   2048
#define DIM   1024
#define HEADS 16
#define DH    64
#define MROWS (BATCH*SEQ)   // 4096

// ---------------- scratch (static device memory; no allocs allowed) --------
__device__ float g_Q[MROWS * DIM];
__device__ float g_K[MROWS * DIM];
__device__ float g_V[MROWS * DIM];
__device__ float g_CTX[MROWS * DIM];
__device__ unsigned short g_xhi[MROWS * DIM];
__device__ unsigned short g_xlo[MROWS * DIM];
__device__ unsigned short g_chi[MROWS * DIM];
__device__ unsigned short g_clo[MROWS * DIM];
__device__ unsigned short g_wqh[DIM * DIM];
__device__ unsigned short g_wql[DIM * DIM];
__device__ unsigned short g_wkh[DIM * DIM];
__device__ unsigned short g_wkl[DIM * DIM];
__device__ unsigned short g_wvh[DIM * DIM];
__device__ unsigned short g_wvl[DIM * DIM];
__device__ unsigned short g_woh[DIM * DIM];
__device__ unsigned short g_wol[DIM * DIM];

// ---------------- helpers ----------------------------------------------------
__device__ __forceinline__ uint32_t smem_to_u32(const void* p) {
    uint32_t a;
    asm("{ .reg .u64 t; cvta.to.shared.u64 t, %1; cvt.u32.u64 %0, t; }"
        : "=r"(a) : "l"(p));
    return a;
}
__device__ __forceinline__ void cp16(uint32_t dst, const void* src) {
    unsigned long long g = __cvta_generic_to_global(src);
    asm volatile("cp.async.cg.shared.global [%0], [%1], 16;" :: "r"(dst), "l"(g));
}
#define CP_COMMIT() asm volatile("cp.async.commit_group;" ::: "memory")
#define CP_WAIT0()  asm volatile("cp.async.wait_group 0;" ::: "memory")
#define CP_WAIT1()  asm volatile("cp.async.wait_group 1;" ::: "memory")

// m16n8k16 row.col bf16 -> f32 HMMA (family-portable, sm_80+)
__device__ __forceinline__ void mma16816(float* c, const uint32_t* a, const uint32_t* b) {
    asm volatile(
        "mma.sync.aligned.m16n8k16.row.col.f32.bf16.bf16.f32 "
        "{%0,%1,%2,%3},{%4,%5,%6,%7},{%8,%9},{%0,%1,%2,%3};"
        : "+f"(c[0]), "+f"(c[1]), "+f"(c[2]), "+f"(c[3])
        : "r"(a[0]), "r"(a[1]), "r"(a[2]), "r"(a[3]), "r"(b[0]), "r"(b[1]));
}

// ---------------- packed f32x2 helpers ---------------------------------------
__device__ __forceinline__ unsigned long long pack2(float a, float b) {
    unsigned long long r;
    asm("mov.b64 %0, {%1,%2};" : "=l"(r) : "f"(a), "f"(b));
    return r;
}
__device__ __forceinline__ void unpack2(unsigned long long v, float& a, float& b) {
    asm("mov.b64 {%0,%1}, %2;" : "=f"(a), "=f"(b) : "l"(v));
}
__device__ __forceinline__ unsigned long long fma2(unsigned long long a,
                                                   unsigned long long b,
                                                   unsigned long long c) {
    unsigned long long d;
    asm("fma.rn.f32x2 %0, %1, %2, %3;" : "=l"(d) : "l"(a), "l"(b), "l"(c));
    return d;
}
__device__ __forceinline__ unsigned long long mul2(unsigned long long a,
                                                   unsigned long long b) {
    unsigned long long d;
    asm("mul.rn.f32x2 %0, %1, %2;" : "=l"(d) : "l"(a), "l"(b));
    return d;
}

// ---------------- split kernels -----------------------------------------------
__device__ __forceinline__ void split1(float v, unsigned short& h, unsigned short& l) {
    __nv_bfloat16 hb = __float2bfloat16(v);
    __nv_bfloat16 lb = __float2bfloat16(v - __bfloat162float(hb));
    h = *(unsigned short*)&hb;
    l = *(unsigned short*)&lb;
}

__global__ __launch_bounds__(256) void split_kernel(
    const float* __restrict__ in, unsigned short* __restrict__ hi,
    unsigned short* __restrict__ lo)
{
    size_t i = ((size_t)blockIdx.x * 256 + threadIdx.x) * 4;
    float4 v = *(const float4*)(in + i);
    ushort4 h, l;
    split1(v.x, h.x, l.x); split1(v.y, h.y, l.y);
    split1(v.z, h.z, l.z); split1(v.w, h.w, l.w);
    *(ushort4*)(hi + i) = h;
    *(ushort4*)(lo + i) = l;
}

// W [K,N] row-major -> Wt_hi/lo [N,K] bf16
__global__ __launch_bounds__(256) void split_transpose_kernel(
    const float* __restrict__ W, unsigned short* __restrict__ hi,
    unsigned short* __restrict__ lo)
{
    __shared__ float t[32][33];
    const int bx = blockIdx.x, by = blockIdx.y;
    const int tx = threadIdx.x, ty = threadIdx.y;
    #pragma unroll
    for (int j = 0; j < 32; j += 8)
        t[ty + j][tx] = W[(size_t)(by * 32 + ty + j) * DIM + bx * 32 + tx];
    __syncthreads();
    #pragma unroll
    for (int j = 0; j < 32; j += 8) {
        float v = t[tx][ty + j];
        unsigned short h, l;
        split1(v, h, l);
        size_t o = (size_t)(bx * 32 + ty + j) * DIM + by * 32 + tx;
        hi[o] = h; lo[o] = l;
    }
}

// ---------------- HMMA bf16x3 GEMM --------------------------------------------
// C[M,N] = A[M,K] @ W[K,N] (+bias). A split hi/lo [M,K]; W pre-transposed+split
// (Bt[N,K]). CTA tile 128x128, BK=32, 8 warps (4m x 2n), warp tile 32x64.
// bf16x3: C = Ah*Bh + Ah*Bl + Al*Bh.
#define KS    40                 // padded row stride (bf16 elems): conflict-free
#define TILE  (128 * KS)         // elems per tile buffer
#define STAGE (4 * TILE)         // Ah, Al, Bh, Bl
#define GEMM_SMEM (2 * STAGE * 2)  // bytes: 2 stages * 4 tiles * 10240B = 81920

__global__ __launch_bounds__(256) void hmma_gemm_kernel(
    const unsigned short* __restrict__ Ahi, const unsigned short* __restrict__ Alo,
    const unsigned short* __restrict__ B0h, const unsigned short* __restrict__ B0l,
    const unsigned short* __restrict__ B1h, const unsigned short* __restrict__ B1l,
    const unsigned short* __restrict__ B2h, const unsigned short* __restrict__ B2l,
    float* __restrict__ C0, float* __restrict__ C1, float* __restrict__ C2,
    const float* __restrict__ bias)
{
    extern __shared__ __align__(16) unsigned short sm[];
    const uint32_t sbase = smem_to_u32(sm);
    const int tid = threadIdx.x;
    const int wid = tid >> 5;
    const int lane = tid & 31;
    const int g   = lane >> 2;     // groupID 0..7
    const int tig = lane & 3;      // thread-in-group

    const int wm = wid & 3;        // 0..3 -> m offset wm*32
    const int wn = wid >> 2;       // 0..1 -> n offset wn*64

    const unsigned short* Bh = (blockIdx.z == 0) ? B0h : (blockIdx.z == 1) ? B1h : B2h;
    const unsigned short* Bl = (blockIdx.z == 0) ? B0l : (blockIdx.z == 1) ? B1l : B2l;
    float* C = (blockIdx.z == 0) ? C0 : (blockIdx.z == 1) ? C1 : C2;

    const int mb = blockIdx.y * 128;
    const int nb = blockIdx.x * 128;

    const unsigned short* Ah0 = Ahi + (size_t)mb * DIM;
    const unsigned short* Al0 = Alo + (size_t)mb * DIM;
    const unsigned short* Bh0 = Bh + (size_t)nb * DIM;
    const unsigned short* Bl0 = Bl + (size_t)nb * DIM;

    // loader: one stage = 4 tiles of 128 rows x 32 bf16 (4 x 16B chunks/row)
    auto load_stage = [&](int s, int k0) {
        const unsigned short* srcs[4] = { Ah0, Al0, Bh0, Bl0 };
        #pragma unroll
        for (int t = 0; t < 4; t++) {
            const unsigned short* gp = srcs[t] + k0;
            uint32_t dbase = sbase + (uint32_t)(s * STAGE + t * TILE) * 2;
            #pragma unroll
            for (int c = 0; c < 2; c++) {
                int idx = tid * 2 + c;          // 0..511
                int row = idx >> 2, cc = idx & 3;
                cp16(dbase + (uint32_t)row * (KS * 2) + cc * 16,
                     gp + (size_t)row * DIM + cc * 8);
            }
        }
        CP_COMMIT();
    };

    float acc[2][8][4];
    #pragma unroll
    for (int im = 0; im < 2; im++)
        #pragma unroll
        for (int in = 0; in < 8; in++)
            #pragma unroll
            for (int r = 0; r < 4; r++) acc[im][in][r] = 0.f;

    const int nk = DIM / 32;   // 32
    load_stage(0, 0);

    for (int kt = 0; kt < nk; kt++) {
        const int s = kt & 1;
        if (kt + 1 < nk) { load_stage(s ^ 1, (kt + 1) * 32); CP_WAIT1(); }
        else             { CP_WAIT0(); }
        __syncthreads();

        const unsigned short* Ahs = sm + s * STAGE;
        const unsigned short* Als = Ahs + TILE;
        const unsigned short* Bhs = Ahs + 2 * TILE;
        const unsigned short* Bls = Ahs + 3 * TILE;

        #pragma unroll
        for (int kk = 0; kk < 32; kk += 16) {
            uint32_t ah[2][4], al[2][4], bh[8][2], bl[8][2];
            #pragma unroll
            for (int im = 0; im < 2; im++) {
                const unsigned short* p = Ahs + (wm * 32 + im * 16 + g) * KS + kk + tig * 2;
                ah[im][0] = *(const uint32_t*)(p);
                ah[im][1] = *(const uint32_t*)(p + 8 * KS);
                ah[im][2] = *(const uint32_t*)(p + 8);
                ah[im][3] = *(const uint32_t*)(p + 8 * KS + 8);
                const unsigned short* q = Als + (wm * 32 + im * 16 + g) * KS + kk + tig * 2;
                al[im][0] = *(const uint32_t*)(q);
                al[im][1] = *(const uint32_t*)(q + 8 * KS);
                al[im][2] = *(const uint32_t*)(q + 8);
                al[im][3] = *(const uint32_t*)(q + 8 * KS + 8);
            }
            #pragma unroll
            for (int in = 0; in < 8; in++) {
                const unsigned short* p = Bhs + (wn * 64 + in * 8 + g) * KS + kk + tig * 2;
                bh[in][0] = *(const uint32_t*)(p);
                bh[in][1] = *(const uint32_t*)(p + 8);
                const unsigned short* q = Bls + (wn * 64 + in * 8 + g) * KS + kk + tig * 2;
                bl[in][0] = *(const uint32_t*)(q);
                bl[in][1] = *(const uint32_t*)(q + 8);
            }
            #pragma unroll
            for (int im = 0; im < 2; im++)
                #pragma unroll
                for (int in = 0; in < 8; in++) {
                    mma16816(acc[im][in], ah[im], bh[in]);
                    mma16816(acc[im][in], ah[im], bl[in]);
                    mma16816(acc[im][in], al[im], bh[in]);
                }
        }
        __syncthreads();
    }

    // epilogue
    #pragma unroll
    for (int im = 0; im < 2; im++) {
        const int row0 = mb + wm * 32 + im * 16 + g;
        #pragma unroll
        for (int in = 0; in < 8; in++) {
            const int col = nb + wn * 64 + in * 8 + tig * 2;
            float b0 = 0.f, b1 = 0.f;
            if (bias) { b0 = bias[col]; b1 = bias[col + 1]; }
            float2 v0 = { acc[im][in][0] + b0, acc[im][in][1] + b1 };
            float2 v1 = { acc[im][in][2] + b0, acc[im][in][3] + b1 };
            *(float2*)(C + (size_t)row0 * DIM + col)       = v0;
            *(float2*)(C + (size_t)(row0 + 8) * DIM + col) = v1;
        }
    }
}

// ---------------- causal flash attention (fp32, tiled 2-GEMM) ------------------
#define FBR 64
#define FBC 64
#define FLASH_SMEM ((64*64 + 68*64 + 64*64) * 4)   // 50176 bytes

__global__ __launch_bounds__(128) void flash2_kernel(
    const float* __restrict__ Q, const float* __restrict__ K,
    const float* __restrict__ V, float* __restrict__ O)
{
    extern __shared__ float smf[];
    float* Qt   = smf;
    float* KtPs = smf + 64 * DH;
    float* Vs   = KtPs + 68 * 64;

    const int tid  = threadIdx.x;
    const int qb   = gridDim.x - 1 - blockIdx.x;
    const int h    = blockIdx.y;
    const int b    = blockIdx.z;
    const int tcol = tid & 7;
    const int trow = tid >> 3;
    const int r0   = trow * 4;
    const int c0   = tcol * 8;

    const float qscale = 0.125f * 1.4426950408889634f;

    const float* Qg = Q + ((size_t)(b * SEQ + qb * FBR)) * DIM + h * DH;
    #pragma unroll
    for (int it = 0; it < 8; it++) {
        int lin = it * 128 + tid;
        int row = lin & 63;
        int dh  = (lin >> 6) << 2;
        float4 v = *(const float4*)(Qg + (size_t)row * DIM + dh);
        Qt[(dh + 0) * 64 + row] = v.x * qscale;
        Qt[(dh + 1) * 64 + row] = v.y * qscale;
        Qt[(dh + 2) * 64 + row] = v.z * qscale;
        Qt[(dh + 3) * 64 + row] = v.w * qscale;
    }

    unsigned long long o2[4][4];
    float m[4], l[4];
    #pragma unroll
    for (int i = 0; i < 4; i++) {
        m[i] = -1e30f; l[i] = 0.f;
        #pragma unroll
        for (int jp = 0; jp < 4; jp++) o2[i][jp] = 0ull;
    }

    for (int kb = 0; kb <= qb; kb++) {
        const float* Kg = K + ((size_t)(b * SEQ + kb * FBC)) * DIM + h * DH;
        const float* Vg = V + ((size_t)(b * SEQ + kb * FBC)) * DIM + h * DH;

        __syncthreads();
        #pragma unroll
        for (int it = 0; it < 8; it++) {
            int lin = it * 128 + tid;
            int row = lin & 63;
            int dh  = (lin >> 6) << 2;
            float4 kv = *(const float4*)(Kg + (size_t)row * DIM + dh);
            KtPs[(dh + 0) * 68 + row] = kv.x;
            KtPs[(dh + 1) * 68 + row] = kv.y;
            KtPs[(dh + 2) * 68 + row] = kv.z;
            KtPs[(dh + 3) * 68 + row] = kv.w;
            *(float4*)(&Vs[row * 64 + dh]) =
                *(const float4*)(Vg + (size_t)row * DIM + dh);
        }
        __syncthreads();

        unsigned long long s2[4][4];
        #pragma unroll
        for (int i = 0; i < 4; i++)
            #pragma unroll
            for (int jp = 0; jp < 4; jp++) s2[i][jp] = 0ull;

        #pragma unroll 8
        for (int dh = 0; dh < DH; dh++) {
            float4 aq = *(const float4*)(&Qt[dh * 64 + r0]);
            ulonglong2 kv0 = *(const ulonglong2*)(&KtPs[dh * 68 + c0]);
            ulonglong2 kv1 = *(const ulonglong2*)(&KtPs[dh * 68 + c0 + 4]);
            unsigned long long br2[4] = { kv0.x, kv0.y, kv1.x, kv1.y };
            unsigned long long ar2[4];
            ar2[0] = pack2(aq.x, aq.x);
            ar2[1] = pack2(aq.y, aq.y);
            ar2[2] = pack2(aq.z, aq.z);
            ar2[3] = pack2(aq.w, aq.w);
            #pragma unroll
            for (int i = 0; i < 4; i++)
                #pragma unroll
                for (int jp = 0; jp < 4; jp++)
                    s2[i][jp] = fma2(ar2[i], br2[jp], s2[i][jp]);
        }
        __syncthreads();

        const bool diag = (kb == qb);
        #pragma unroll
        for (int i = 0; i < 4; i++) {
            float sv[8];
            #pragma unroll
            for (int jp = 0; jp < 4; jp++)
                unpack2(s2[i][jp], sv[2 * jp], sv[2 * jp + 1]);
            if (diag) {
                #pragma unroll
                for (int j = 0; j < 8; j++)
                    if (c0 + j > r0 + i) sv[j] = -1e30f;
            }
            float mx = sv[0];
            #pragma unroll
            for (int j = 1; j < 8; j++) mx = fmaxf(mx, sv[j]);
            mx = fmaxf(mx, __shfl_xor_sync(0xffffffffu, mx, 1));
            mx = fmaxf(mx, __shfl_xor_sync(0xffffffffu, mx, 2));
            mx = fmaxf(mx, __shfl_xor_sync(0xffffffffu, mx, 4));

            float mn   = fmaxf(m[i], mx);
            float corr = exp2f(m[i] - mn);
            m[i] = mn;

            float rs = 0.f;
            #pragma unroll
            for (int j = 0; j < 8; j++) { sv[j] = exp2f(sv[j] - mn); rs += sv[j]; }
            rs += __shfl_xor_sync(0xffffffffu, rs, 1);
            rs += __shfl_xor_sync(0xffffffffu, rs, 2);
            rs += __shfl_xor_sync(0xffffffffu, rs, 4);
            l[i] = l[i] * corr + rs;

            unsigned long long c2 = pack2(corr, corr);
            #pragma unroll
            for (int jp = 0; jp < 4; jp++) o2[i][jp] = mul2(o2[i][jp], c2);

            float4 p0 = { sv[0], sv[1], sv[2], sv[3] };
            float4 p1 = { sv[4], sv[5], sv[6], sv[7] };
            *(float4*)(&KtPs[(r0 + i) * 68 + c0])     = p0;
            *(float4*)(&KtPs[(r0 + i) * 68 + c0 + 4]) = p1;
        }
        __syncthreads();

        #pragma unroll 4
        for (int k4 = 0; k4 < FBC; k4 += 4) {
            float pa[4][4];
            #pragma unroll
            for (int i = 0; i < 4; i++)
                *(float4*)pa[i] = *(const float4*)(&KtPs[(r0 + i) * 68 + k4]);
            #pragma unroll
            for (int kk = 0; kk < 4; kk++) {
                ulonglong2 v0 = *(const ulonglong2*)(&Vs[(k4 + kk) * 64 + c0]);
                ulonglong2 v1 = *(const ulonglong2*)(&Vs[(k4 + kk) * 64 + c0 + 4]);
                unsigned long long br2[4] = { v0.x, v0.y, v1.x, v1.y };
                #pragma unroll
                for (int i = 0; i < 4; i++) {
                    unsigned long long a2 = pack2(pa[i][kk], pa[i][kk]);
                    #pragma unroll
                    for (int jp = 0; jp < 4; jp++)
                        o2[i][jp] = fma2(a2, br2[jp], o2[i][jp]);
                }
            }
        }
    }

    float* Og = O + ((size_t)(b * SEQ + qb * FBR)) * DIM + h * DH;
    #pragma unroll
    for (int i = 0; i < 4; i++) {
        const float inv = 1.0f / l[i];
        float ov[8];
        #pragma unroll
        for (int jp = 0; jp < 4; jp++)
            unpack2(o2[i][jp], ov[2 * jp], ov[2 * jp + 1]);
        #pragma unroll
        for (int j = 0; j < 8; j++) ov[j] *= inv;
        float4 v0 = { ov[0], ov[1], ov[2], ov[3] };
        float4 v1 = { ov[4], ov[5], ov[6], ov[7] };
        *(float4*)(Og + (size_t)(r0 + i) * DIM + c0)     = v0;
        *(float4*)(Og + (size_t)(r0 + i) * DIM + c0 + 4) = v1;
    }
}

// ---------------- launch --------------------------------------------------------
extern "C" void kernel_launch(void* const* d_in, const int* in_sizes, int n_in,
                              void* d_out, int out_size)
{
    const float* x  = (const float*)d_in[0];
    const float* Wq = (const float*)d_in[1];
    const float* Wk = (const float*)d_in[2];
    const float* Wv = (const float*)d_in[3];
    const float* Wo = (const float*)d_in[4];
    const float* bo = (const float*)d_in[5];
    float* out = (float*)d_out;

    float *Qp, *Kp, *Vp, *Cp;
    cudaGetSymbolAddress((void**)&Qp, g_Q);
    cudaGetSymbolAddress((void**)&Kp, g_K);
    cudaGetSymbolAddress((void**)&Vp, g_V);
    cudaGetSymbolAddress((void**)&Cp, g_CTX);

    unsigned short *xhi, *xlo, *chi, *clo;
    unsigned short *wqh, *wql, *wkh, *wkl, *wvh, *wvl, *woh, *wol;
    cudaGetSymbolAddress((void**)&xhi, g_xhi);
    cudaGetSymbolAddress((void**)&xlo, g_xlo);
    cudaGetSymbolAddress((void**)&chi, g_chi);
    cudaGetSymbolAddress((void**)&clo, g_clo);
    cudaGetSymbolAddress((void**)&wqh, g_wqh);
    cudaGetSymbolAddress((void**)&wql, g_wql);
    cudaGetSymbolAddress((void**)&wkh, g_wkh);
    cudaGetSymbolAddress((void**)&wkl, g_wkl);
    cudaGetSymbolAddress((void**)&wvh, g_wvh);
    cudaGetSymbolAddress((void**)&wvl, g_wvl);
    cudaGetSymbolAddress((void**)&woh, g_woh);
    cudaGetSymbolAddress((void**)&wol, g_wol);

    cudaFuncSetAttribute(flash2_kernel,
                         cudaFuncAttributeMaxDynamicSharedMemorySize, FLASH_SMEM);
    cudaFuncSetAttribute(hmma_gemm_kernel,
                         cudaFuncAttributeMaxDynamicSharedMemorySize, GEMM_SMEM);

    // 1) split x and weights into bf16 hi/lo (weights transposed to [N,K])
    split_kernel<<<MROWS * DIM / 1024, 256>>>(x, xhi, xlo);
    dim3 tg(DIM / 32, DIM / 32), tb(32, 8);
    split_transpose_kernel<<<tg, tb>>>(Wq, wqh, wql);
    split_transpose_kernel<<<tg, tb>>>(Wk, wkh, wkl);
    split_transpose_kernel<<<tg, tb>>>(Wv, wvh, wvl);
    split_transpose_kernel<<<tg, tb>>>(Wo, woh, wol);

    // 2) fused QKV projections on tensor cores (HMMA bf16x3)
    dim3 qkv_grid(DIM / 128, MROWS / 128, 3);   // (8, 32, 3)
    hmma_gemm_kernel<<<qkv_grid, 256, GEMM_SMEM>>>(
        xhi, xlo, wqh, wql, wkh, wkl, wvh, wvl,
        Qp, Kp, Vp, nullptr);

    // 3) causal attention
    dim3 fa_grid(SEQ / FBR, HEADS, BATCH);
    flash2_kernel<<<fa_grid, 128, FLASH_SMEM>>>(Qp, Kp, Vp, Cp);

    // 4) split ctx, then O-projection (+bias) on tensor cores
    split_kernel<<<MROWS * DIM / 1024, 256>>>(Cp, chi, clo);
    dim3 o_grid(DIM / 128, MROWS / 128, 1);
    hmma_gemm_kernel<<<o_grid, 256, GEMM_SMEM>>>(
        chi, clo, woh, wol, woh, wol, woh, wol,
        out, out, out, bo);
}

// round 6
// speedup vs baseline: 3.2312x; 1.9959x over previous
#include <cuda_runtime.h>
#include <cuda_bf16.h>
#include <stdint.h>
#include <math.h>

// Problem shape (fixed by reference setup_inputs)
#define BATCH 2
#define SEQ   2048
#define DIM   1024
#define HEADS 16
#define DH    64
#define MROWS (BATCH*SEQ)   // 4096

// ---------------- scratch (static device memory; no allocs allowed) --------
__device__ float g_CTX[MROWS * DIM];
__device__ unsigned short g_xhi[MROWS * DIM];
__device__ unsigned short g_xlo[MROWS * DIM];
__device__ unsigned short g_chi[MROWS * DIM];
__device__ unsigned short g_clo[MROWS * DIM];
__device__ unsigned short g_qhi[MROWS * DIM];
__device__ unsigned short g_qlo[MROWS * DIM];
__device__ unsigned short g_khi[MROWS * DIM];
__device__ unsigned short g_klo[MROWS * DIM];
__device__ unsigned short g_vhi[MROWS * DIM];
__device__ unsigned short g_vlo[MROWS * DIM];
__device__ unsigned short g_vthi[MROWS * DIM];
__device__ unsigned short g_vtlo[MROWS * DIM];
__device__ unsigned short g_wqh[DIM * DIM];
__device__ unsigned short g_wql[DIM * DIM];
__device__ unsigned short g_wkh[DIM * DIM];
__device__ unsigned short g_wkl[DIM * DIM];
__device__ unsigned short g_wvh[DIM * DIM];
__device__ unsigned short g_wvl[DIM * DIM];
__device__ unsigned short g_woh[DIM * DIM];
__device__ unsigned short g_wol[DIM * DIM];

// ---------------- helpers ----------------------------------------------------
__device__ __forceinline__ uint32_t smem_to_u32(const void* p) {
    uint32_t a;
    asm("{ .reg .u64 t; cvta.to.shared.u64 t, %1; cvt.u32.u64 %0, t; }"
        : "=r"(a) : "l"(p));
    return a;
}
__device__ __forceinline__ void cp16(uint32_t dst, const void* src) {
    unsigned long long g = __cvta_generic_to_global(src);
    asm volatile("cp.async.cg.shared.global [%0], [%1], 16;" :: "r"(dst), "l"(g));
}
#define CP_COMMIT() asm volatile("cp.async.commit_group;" ::: "memory")
#define CP_WAIT0()  asm volatile("cp.async.wait_group 0;" ::: "memory")
#define CP_WAIT1()  asm volatile("cp.async.wait_group 1;" ::: "memory")

// m16n8k16 row.col bf16 -> f32 HMMA (family-portable, sm_80+)
__device__ __forceinline__ void mma16816(float* c, const uint32_t* a, const uint32_t* b) {
    asm volatile(
        "mma.sync.aligned.m16n8k16.row.col.f32.bf16.bf16.f32 "
        "{%0,%1,%2,%3},{%4,%5,%6,%7},{%8,%9},{%0,%1,%2,%3};"
        : "+f"(c[0]), "+f"(c[1]), "+f"(c[2]), "+f"(c[3])
        : "r"(a[0]), "r"(a[1]), "r"(a[2]), "r"(a[3]), "r"(b[0]), "r"(b[1]));
}

__device__ __forceinline__ float ex2f(float x) {
    float r;
    asm("ex2.approx.f32 %0, %1;" : "=f"(r) : "f"(x));
    return r;
}

// split two floats into packed bf16x2 hi (returned) and lo (*lop).
// low ushort = first arg (lower k index), high ushort = second arg.
__device__ __forceinline__ uint32_t bsplit2(float a, float b, uint32_t* lop) {
    __nv_bfloat16 ah = __float2bfloat16(a), bh = __float2bfloat16(b);
    __nv_bfloat16 al = __float2bfloat16(a - __bfloat162float(ah));
    __nv_bfloat16 bl = __float2bfloat16(b - __bfloat162float(bh));
    uint32_t hi = ((uint32_t)(*(unsigned short*)&bh) << 16) | (*(unsigned short*)&ah);
    *lop = ((uint32_t)(*(unsigned short*)&bl) << 16) | (*(unsigned short*)&al);
    return hi;
}

// ---------------- split kernels -----------------------------------------------
__device__ __forceinline__ void split1(float v, unsigned short& h, unsigned short& l) {
    __nv_bfloat16 hb = __float2bfloat16(v);
    __nv_bfloat16 lb = __float2bfloat16(v - __bfloat162float(hb));
    h = *(unsigned short*)&hb;
    l = *(unsigned short*)&lb;
}

__global__ __launch_bounds__(256) void split_kernel(
    const float* __restrict__ in, unsigned short* __restrict__ hi,
    unsigned short* __restrict__ lo)
{
    size_t i = ((size_t)blockIdx.x * 256 + threadIdx.x) * 4;
    float4 v = *(const float4*)(in + i);
    ushort4 h, l;
    split1(v.x, h.x, l.x); split1(v.y, h.y, l.y);
    split1(v.z, h.z, l.z); split1(v.w, h.w, l.w);
    *(ushort4*)(hi + i) = h;
    *(ushort4*)(lo + i) = l;
}

// W [K,N] row-major -> Wt_hi/lo [N,K] bf16
__global__ __launch_bounds__(256) void split_transpose_kernel(
    const float* __restrict__ W, unsigned short* __restrict__ hi,
    unsigned short* __restrict__ lo)
{
    __shared__ float t[32][33];
    const int bx = blockIdx.x, by = blockIdx.y;
    const int tx = threadIdx.x, ty = threadIdx.y;
    #pragma unroll
    for (int j = 0; j < 32; j += 8)
        t[ty + j][tx] = W[(size_t)(by * 32 + ty + j) * DIM + bx * 32 + tx];
    __syncthreads();
    #pragma unroll
    for (int j = 0; j < 32; j += 8) {
        float v = t[tx][ty + j];
        unsigned short h, l;
        split1(v, h, l);
        size_t o = (size_t)(bx * 32 + ty + j) * DIM + by * 32 + tx;
        hi[o] = h; lo[o] = l;
    }
}

// V hi/lo [s][dim] -> Vt hi/lo [b][h][dh][s]   (per-head 64x64 tile transpose)
__global__ __launch_bounds__(256) void vt_kernel(
    const unsigned short* __restrict__ vhi, const unsigned short* __restrict__ vlo,
    unsigned short* __restrict__ vthi, unsigned short* __restrict__ vtlo)
{
    __shared__ unsigned short Th[64][65], Tl[64][65];
    const int s0 = blockIdx.x * 64;
    const int h  = blockIdx.y;
    const int b  = blockIdx.z;
    const int tx = threadIdx.x & 63, ty = threadIdx.x >> 6;   // 64 x 4
    #pragma unroll
    for (int r = ty; r < 64; r += 4) {
        size_t src = (size_t)(b * SEQ + s0 + r) * DIM + h * DH + tx;
        Th[r][tx] = vhi[src];
        Tl[r][tx] = vlo[src];
    }
    __syncthreads();
    #pragma unroll
    for (int d = ty; d < 64; d += 4) {
        size_t dst = ((size_t)((b * HEADS + h) * DH + d)) * SEQ + s0 + tx;
        vthi[dst] = Th[tx][d];
        vtlo[dst] = Tl[tx][d];
    }
}

// ---------------- HMMA bf16x3 GEMM --------------------------------------------
// C[M,N] = A[M,K] @ W[K,N]. A split hi/lo [M,K]; W pre-transposed+split Bt[N,K].
// CTA 128x128, BK=32, 8 warps (4m x 2n), warp tile 32x64.
// Output: fp32 C (+bias)  OR  split bf16 hi/lo (when H0 != null).
#define KS    40
#define TILE  (128 * KS)
#define STAGE (4 * TILE)
#define GEMM_SMEM (2 * STAGE * 2)   // 81920 bytes

__global__ __launch_bounds__(256) void hmma_gemm_kernel(
    const unsigned short* __restrict__ Ahi, const unsigned short* __restrict__ Alo,
    const unsigned short* __restrict__ B0h, const unsigned short* __restrict__ B0l,
    const unsigned short* __restrict__ B1h, const unsigned short* __restrict__ B1l,
    const unsigned short* __restrict__ B2h, const unsigned short* __restrict__ B2l,
    float* __restrict__ C, const float* __restrict__ bias,
    unsigned short* __restrict__ H0, unsigned short* __restrict__ L0,
    unsigned short* __restrict__ H1, unsigned short* __restrict__ L1,
    unsigned short* __restrict__ H2, unsigned short* __restrict__ L2)
{
    extern __shared__ __align__(16) unsigned short smg[];
    const uint32_t sbase = smem_to_u32(smg);
    const int tid = threadIdx.x;
    const int wid = tid >> 5;
    const int lane = tid & 31;
    const int g   = lane >> 2;
    const int tig = lane & 3;
    const int wm = wid & 3;
    const int wn = wid >> 2;

    const unsigned short* Bh = (blockIdx.z == 0) ? B0h : (blockIdx.z == 1) ? B1h : B2h;
    const unsigned short* Bl = (blockIdx.z == 0) ? B0l : (blockIdx.z == 1) ? B1l : B2l;
    unsigned short* Hi = (blockIdx.z == 0) ? H0 : (blockIdx.z == 1) ? H1 : H2;
    unsigned short* Lo = (blockIdx.z == 0) ? L0 : (blockIdx.z == 1) ? L1 : L2;

    const int mb = blockIdx.y * 128;
    const int nb = blockIdx.x * 128;

    const unsigned short* Ah0 = Ahi + (size_t)mb * DIM;
    const unsigned short* Al0 = Alo + (size_t)mb * DIM;
    const unsigned short* Bh0 = Bh + (size_t)nb * DIM;
    const unsigned short* Bl0 = Bl + (size_t)nb * DIM;

    auto load_stage = [&](int s, int k0) {
        const unsigned short* srcs[4] = { Ah0, Al0, Bh0, Bl0 };
        #pragma unroll
        for (int t = 0; t < 4; t++) {
            const unsigned short* gp = srcs[t] + k0;
            uint32_t dbase = sbase + (uint32_t)(s * STAGE + t * TILE) * 2;
            #pragma unroll
            for (int c = 0; c < 2; c++) {
                int idx = tid * 2 + c;
                int row = idx >> 2, cc = idx & 3;
                cp16(dbase + (uint32_t)row * (KS * 2) + cc * 16,
                     gp + (size_t)row * DIM + cc * 8);
            }
        }
        CP_COMMIT();
    };

    float acc[2][8][4];
    #pragma unroll
    for (int im = 0; im < 2; im++)
        #pragma unroll
        for (int in = 0; in < 8; in++)
            #pragma unroll
            for (int r = 0; r < 4; r++) acc[im][in][r] = 0.f;

    const int nk = DIM / 32;
    load_stage(0, 0);

    for (int kt = 0; kt < nk; kt++) {
        const int s = kt & 1;
        if (kt + 1 < nk) { load_stage(s ^ 1, (kt + 1) * 32); CP_WAIT1(); }
        else             { CP_WAIT0(); }
        __syncthreads();

        const unsigned short* Ahs = smg + s * STAGE;
        const unsigned short* Als = Ahs + TILE;
        const unsigned short* Bhs = Ahs + 2 * TILE;
        const unsigned short* Bls = Ahs + 3 * TILE;

        #pragma unroll
        for (int kk = 0; kk < 32; kk += 16) {
            uint32_t ah[2][4], al[2][4], bh[8][2], bl[8][2];
            #pragma unroll
            for (int im = 0; im < 2; im++) {
                const unsigned short* p = Ahs + (wm * 32 + im * 16 + g) * KS + kk + tig * 2;
                ah[im][0] = *(const uint32_t*)(p);
                ah[im][1] = *(const uint32_t*)(p + 8 * KS);
                ah[im][2] = *(const uint32_t*)(p + 8);
                ah[im][3] = *(const uint32_t*)(p + 8 * KS + 8);
                const unsigned short* q = Als + (wm * 32 + im * 16 + g) * KS + kk + tig * 2;
                al[im][0] = *(const uint32_t*)(q);
                al[im][1] = *(const uint32_t*)(q + 8 * KS);
                al[im][2] = *(const uint32_t*)(q + 8);
                al[im][3] = *(const uint32_t*)(q + 8 * KS + 8);
            }
            #pragma unroll
            for (int in = 0; in < 8; in++) {
                const unsigned short* p = Bhs + (wn * 64 + in * 8 + g) * KS + kk + tig * 2;
                bh[in][0] = *(const uint32_t*)(p);
                bh[in][1] = *(const uint32_t*)(p + 8);
                const unsigned short* q = Bls + (wn * 64 + in * 8 + g) * KS + kk + tig * 2;
                bl[in][0] = *(const uint32_t*)(q);
                bl[in][1] = *(const uint32_t*)(q + 8);
            }
            #pragma unroll
            for (int im = 0; im < 2; im++)
                #pragma unroll
                for (int in = 0; in < 8; in++) {
                    mma16816(acc[im][in], ah[im], bh[in]);
                    mma16816(acc[im][in], ah[im], bl[in]);
                    mma16816(acc[im][in], al[im], bh[in]);
                }
        }
        __syncthreads();
    }

    // epilogue
    #pragma unroll
    for (int im = 0; im < 2; im++) {
        const int row0 = mb + wm * 32 + im * 16 + g;
        #pragma unroll
        for (int in = 0; in < 8; in++) {
            const int col = nb + wn * 64 + in * 8 + tig * 2;
            if (Hi) {
                uint32_t lo0, lo1;
                uint32_t hi0 = bsplit2(acc[im][in][0], acc[im][in][1], &lo0);
                uint32_t hi1 = bsplit2(acc[im][in][2], acc[im][in][3], &lo1);
                *(uint32_t*)(Hi + (size_t)row0 * DIM + col)       = hi0;
                *(uint32_t*)(Lo + (size_t)row0 * DIM + col)       = lo0;
                *(uint32_t*)(Hi + (size_t)(row0 + 8) * DIM + col) = hi1;
                *(uint32_t*)(Lo + (size_t)(row0 + 8) * DIM + col) = lo1;
            } else {
                float b0 = 0.f, b1 = 0.f;
                if (bias) { b0 = bias[col]; b1 = bias[col + 1]; }
                float2 v0 = { acc[im][in][0] + b0, acc[im][in][1] + b1 };
                float2 v1 = { acc[im][in][2] + b0, acc[im][in][3] + b1 };
                *(float2*)(C + (size_t)row0 * DIM + col)       = v0;
                *(float2*)(C + (size_t)(row0 + 8) * DIM + col) = v1;
            }
        }
    }
}

// ---------------- HMMA causal flash attention ----------------------------------
// Block: 128 q-rows of one (b,h); 8 warps, 16 rows each. KV tiles of 64 keys,
// double-buffered cp.async. bf16x3 in both GEMMs. P stays in registers.
#define FKS   72                      // padded smem row (bf16 elems) -> conflict-free
#define FTILE (64 * FKS)              // ushorts per tile
#define FSTAGE (4 * FTILE)            // Khi,Klo,Vhi,Vlo
#define FLASH_SMEM (2 * FSTAGE * 2)   // 73728 bytes

__global__ __launch_bounds__(256, 2) void flash_hmma_kernel(
    const unsigned short* __restrict__ qhi, const unsigned short* __restrict__ qlo,
    const unsigned short* __restrict__ khi, const unsigned short* __restrict__ klo,
    const unsigned short* __restrict__ vthi, const unsigned short* __restrict__ vtlo,
    float* __restrict__ O)
{
    extern __shared__ __align__(16) unsigned short smf[];
    const uint32_t sbase = smem_to_u32(smf);
    const int tid = threadIdx.x;
    const int wid = tid >> 5;
    const int lane = tid & 31;
    const int g = lane >> 2, tig = lane & 3;
    const int qb = gridDim.x - 1 - blockIdx.x;     // big tiles first
    const int h = blockIdx.y, b = blockIdx.z;

    const int row0 = qb * 128 + wid * 16 + g;      // rows row0, row0+8

    const int nkb = 2 * qb + 2;

    auto load_stage = [&](int s, int kb) {
        const unsigned short* srcs[4];
        srcs[0] = khi  + (size_t)(b * SEQ + kb * 64) * DIM + h * DH;
        srcs[1] = klo  + (size_t)(b * SEQ + kb * 64) * DIM + h * DH;
        srcs[2] = vthi + ((size_t)((b * HEADS + h) * DH)) * SEQ + kb * 64;
        srcs[3] = vtlo + ((size_t)((b * HEADS + h) * DH)) * SEQ + kb * 64;
        const int strides[4] = { DIM, DIM, SEQ, SEQ };
        uint32_t dst0 = sbase + (uint32_t)(s * FSTAGE) * 2;
        #pragma unroll
        for (int it = 0; it < 8; it++) {
            int c = it * 256 + tid;       // 0..2047
            int t  = c >> 9;              // tile
            int r  = (c >> 3) & 63;       // row
            int ck = c & 7;               // 16B chunk
            cp16(dst0 + (uint32_t)(t * FTILE) * 2 + r * (FKS * 2) + ck * 16,
                 srcs[t] + (size_t)r * strides[t] + ck * 8);
        }
        CP_COMMIT();
    };

    load_stage(0, 0);

    // Q fragments (direct LDG, once per block)
    uint32_t qa_h[4][4], qa_l[4][4];
    {
        const unsigned short* qbh = qhi + (size_t)(b * SEQ + qb * 128 + wid * 16) * DIM + h * DH;
        const unsigned short* qbl = qlo + (size_t)(b * SEQ + qb * 128 + wid * 16) * DIM + h * DH;
        #pragma unroll
        for (int kf = 0; kf < 4; kf++) {
            int ko = kf * 16 + tig * 2;
            qa_h[kf][0] = *(const uint32_t*)(qbh + (size_t)g * DIM + ko);
            qa_h[kf][1] = *(const uint32_t*)(qbh + (size_t)(g + 8) * DIM + ko);
            qa_h[kf][2] = *(const uint32_t*)(qbh + (size_t)g * DIM + ko + 8);
            qa_h[kf][3] = *(const uint32_t*)(qbh + (size_t)(g + 8) * DIM + ko + 8);
            qa_l[kf][0] = *(const uint32_t*)(qbl + (size_t)g * DIM + ko);
            qa_l[kf][1] = *(const uint32_t*)(qbl + (size_t)(g + 8) * DIM + ko);
            qa_l[kf][2] = *(const uint32_t*)(qbl + (size_t)g * DIM + ko + 8);
            qa_l[kf][3] = *(const uint32_t*)(qbl + (size_t)(g + 8) * DIM + ko + 8);
        }
    }

    float oacc[8][4];
    #pragma unroll
    for (int nf = 0; nf < 8; nf++)
        #pragma unroll
        for (int e = 0; e < 4; e++) oacc[nf][e] = 0.f;
    float m0 = -1e30f, m1 = -1e30f, l0 = 0.f, l1 = 0.f;

    const float qscale = 0.125f * 1.4426950408889634f;   // 1/sqrt(64) * log2(e)

    for (int kb = 0; kb < nkb; kb++) {
        const int s = kb & 1;
        if (kb + 1 < nkb) { load_stage(s ^ 1, kb + 1); CP_WAIT1(); }
        else              { CP_WAIT0(); }
        __syncthreads();

        const unsigned short* Kh = smf + s * FSTAGE;
        const unsigned short* Kl = Kh + FTILE;
        const unsigned short* Vh = Kh + 2 * FTILE;
        const unsigned short* Vl = Kh + 3 * FTILE;

        // ---- S = Q K^T (bf16x3) ----
        float sfr[8][4];
        #pragma unroll
        for (int nf = 0; nf < 8; nf++)
            #pragma unroll
            for (int e = 0; e < 4; e++) sfr[nf][e] = 0.f;

        #pragma unroll
        for (int kf = 0; kf < 4; kf++) {
            const int ko = kf * 16 + tig * 2;
            #pragma unroll
            for (int nf = 0; nf < 8; nf++) {
                const unsigned short* ph = Kh + (nf * 8 + g) * FKS + ko;
                const unsigned short* pl = Kl + (nf * 8 + g) * FKS + ko;
                uint32_t bh[2] = { *(const uint32_t*)ph, *(const uint32_t*)(ph + 8) };
                uint32_t bl[2] = { *(const uint32_t*)pl, *(const uint32_t*)(pl + 8) };
                mma16816(sfr[nf], qa_h[kf], bh);
                mma16816(sfr[nf], qa_l[kf], bh);
                mma16816(sfr[nf], qa_h[kf], bl);
            }
        }

        // ---- online softmax in fragment layout ----
        const bool needmask = (kb >= 2 * qb);
        float tm0 = -1e30f, tm1 = -1e30f;
        #pragma unroll
        for (int nf = 0; nf < 8; nf++) {
            #pragma unroll
            for (int e = 0; e < 4; e++) {
                float sv = sfr[nf][e] * qscale;
                if (needmask) {
                    int col = kb * 64 + nf * 8 + tig * 2 + (e & 1);
                    int rr  = (e < 2) ? row0 : (row0 + 8);
                    if (col > rr) sv = -1e30f;
                }
                sfr[nf][e] = sv;
            }
            tm0 = fmaxf(tm0, fmaxf(sfr[nf][0], sfr[nf][1]));
            tm1 = fmaxf(tm1, fmaxf(sfr[nf][2], sfr[nf][3]));
        }
        tm0 = fmaxf(tm0, __shfl_xor_sync(0xffffffffu, tm0, 1));
        tm0 = fmaxf(tm0, __shfl_xor_sync(0xffffffffu, tm0, 2));
        tm1 = fmaxf(tm1, __shfl_xor_sync(0xffffffffu, tm1, 1));
        tm1 = fmaxf(tm1, __shfl_xor_sync(0xffffffffu, tm1, 2));

        const float mn0 = fmaxf(m0, tm0), mn1 = fmaxf(m1, tm1);
        const float c0 = ex2f(m0 - mn0), c1 = ex2f(m1 - mn1);
        m0 = mn0; m1 = mn1;

        float rs0 = 0.f, rs1 = 0.f;
        #pragma unroll
        for (int nf = 0; nf < 8; nf++) {
            sfr[nf][0] = ex2f(sfr[nf][0] - mn0);
            sfr[nf][1] = ex2f(sfr[nf][1] - mn0);
            sfr[nf][2] = ex2f(sfr[nf][2] - mn1);
            sfr[nf][3] = ex2f(sfr[nf][3] - mn1);
            rs0 += sfr[nf][0] + sfr[nf][1];
            rs1 += sfr[nf][2] + sfr[nf][3];
        }
        rs0 += __shfl_xor_sync(0xffffffffu, rs0, 1);
        rs0 += __shfl_xor_sync(0xffffffffu, rs0, 2);
        rs1 += __shfl_xor_sync(0xffffffffu, rs1, 1);
        rs1 += __shfl_xor_sync(0xffffffffu, rs1, 2);
        l0 = l0 * c0 + rs0;
        l1 = l1 * c1 + rs1;

        #pragma unroll
        for (int nf = 0; nf < 8; nf++) {
            oacc[nf][0] *= c0; oacc[nf][1] *= c0;
            oacc[nf][2] *= c1; oacc[nf][3] *= c1;
        }

        // ---- O += P V (bf16x3; P from registers) ----
        #pragma unroll
        for (int kc = 0; kc < 4; kc++) {
            uint32_t pah[4], pal[4];
            pah[0] = bsplit2(sfr[2*kc][0],     sfr[2*kc][1],     &pal[0]);
            pah[1] = bsplit2(sfr[2*kc][2],     sfr[2*kc][3],     &pal[1]);
            pah[2] = bsplit2(sfr[2*kc + 1][0], sfr[2*kc + 1][1], &pal[2]);
            pah[3] = bsplit2(sfr[2*kc + 1][2], sfr[2*kc + 1][3], &pal[3]);
            const int vo = kc * 16 + tig * 2;
            #pragma unroll
            for (int nf = 0; nf < 8; nf++) {
                const unsigned short* ph = Vh + (nf * 8 + g) * FKS + vo;
                const unsigned short* pl = Vl + (nf * 8 + g) * FKS + vo;
                uint32_t bh[2] = { *(const uint32_t*)ph, *(const uint32_t*)(ph + 8) };
                uint32_t bl[2] = { *(const uint32_t*)pl, *(const uint32_t*)(pl + 8) };
                mma16816(oacc[nf], pah, bh);
                mma16816(oacc[nf], pal, bh);
                mma16816(oacc[nf], pah, bl);
            }
        }
        __syncthreads();
    }

    // ---- normalize + store ----
    const float inv0 = 1.f / l0, inv1 = 1.f / l1;
    #pragma unroll
    for (int nf = 0; nf < 8; nf++) {
        const int col = h * DH + nf * 8 + tig * 2;
        float2 v0 = { oacc[nf][0] * inv0, oacc[nf][1] * inv0 };
        float2 v1 = { oacc[nf][2] * inv1, oacc[nf][3] * inv1 };
        *(float2*)(O + (size_t)(b * SEQ + row0) * DIM + col)     = v0;
        *(float2*)(O + (size_t)(b * SEQ + row0 + 8) * DIM + col) = v1;
    }
}

// ---------------- launch ---------------------------------------------------------
extern "C" void kernel_launch(void* const* d_in, const int* in_sizes, int n_in,
                              void* d_out, int out_size)
{
    const float* x  = (const float*)d_in[0];
    const float* Wq = (const float*)d_in[1];
    const float* Wk = (const float*)d_in[2];
    const float* Wv = (const float*)d_in[3];
    const float* Wo = (const float*)d_in[4];
    const float* bo = (const float*)d_in[5];
    float* out = (float*)d_out;

    float* Cp;
    cudaGetSymbolAddress((void**)&Cp, g_CTX);

    unsigned short *xhi, *xlo, *chi, *clo;
    unsigned short *qhi, *qlo, *khi, *klo, *vhi, *vlo, *vthi, *vtlo;
    unsigned short *wqh, *wql, *wkh, *wkl, *wvh, *wvl, *woh, *wol;
    cudaGetSymbolAddress((void**)&xhi, g_xhi);
    cudaGetSymbolAddress((void**)&xlo, g_xlo);
    cudaGetSymbolAddress((void**)&chi, g_chi);
    cudaGetSymbolAddress((void**)&clo, g_clo);
    cudaGetSymbolAddress((void**)&qhi, g_qhi);
    cudaGetSymbolAddress((void**)&qlo, g_qlo);
    cudaGetSymbolAddress((void**)&khi, g_khi);
    cudaGetSymbolAddress((void**)&klo, g_klo);
    cudaGetSymbolAddress((void**)&vhi, g_vhi);
    cudaGetSymbolAddress((void**)&vlo, g_vlo);
    cudaGetSymbolAddress((void**)&vthi, g_vthi);
    cudaGetSymbolAddress((void**)&vtlo, g_vtlo);
    cudaGetSymbolAddress((void**)&wqh, g_wqh);
    cudaGetSymbolAddress((void**)&wql, g_wql);
    cudaGetSymbolAddress((void**)&wkh, g_wkh);
    cudaGetSymbolAddress((void**)&wkl, g_wkl);
    cudaGetSymbolAddress((void**)&wvh, g_wvh);
    cudaGetSymbolAddress((void**)&wvl, g_wvl);
    cudaGetSymbolAddress((void**)&woh, g_woh);
    cudaGetSymbolAddress((void**)&wol, g_wol);

    cudaFuncSetAttribute(hmma_gemm_kernel,
                         cudaFuncAttributeMaxDynamicSharedMemorySize, GEMM_SMEM);
    cudaFuncSetAttribute(flash_hmma_kernel,
                         cudaFuncAttributeMaxDynamicSharedMemorySize, FLASH_SMEM);

    // 1) split x and weights into bf16 hi/lo (weights transposed to [N,K])
    split_kernel<<<MROWS * DIM / 1024, 256>>>(x, xhi, xlo);
    dim3 tg(DIM / 32, DIM / 32), tb(32, 8);
    split_transpose_kernel<<<tg, tb>>>(Wq, wqh, wql);
    split_transpose_kernel<<<tg, tb>>>(Wk, wkh, wkl);
    split_transpose_kernel<<<tg, tb>>>(Wv, wvh, wvl);
    split_transpose_kernel<<<tg, tb>>>(Wo, woh, wol);

    // 2) fused QKV projections -> split bf16 hi/lo outputs directly
    dim3 qkv_grid(DIM / 128, MROWS / 128, 3);
    hmma_gemm_kernel<<<qkv_grid, 256, GEMM_SMEM>>>(
        xhi, xlo, wqh, wql, wkh, wkl, wvh, wvl,
        nullptr, nullptr, qhi, qlo, khi, klo, vhi, vlo);

    // 3) per-head transpose of V for the PV GEMM
    dim3 vt_grid(SEQ / 64, HEADS, BATCH);
    vt_kernel<<<vt_grid, 256>>>(vhi, vlo, vthi, vtlo);

    // 4) causal flash attention on tensor cores
    dim3 fa_grid(SEQ / 128, HEADS, BATCH);   // (16, 16, 2)
    flash_hmma_kernel<<<fa_grid, 256, FLASH_SMEM>>>(
        qhi, qlo, khi, klo, vthi, vtlo, Cp);

    // 5) split ctx, then O-projection (+bias) -> fp32 out
    split_kernel<<<MROWS * DIM / 1024, 256>>>(Cp, chi, clo);
    dim3 o_grid(DIM / 128, MROWS / 128, 1);
    hmma_gemm_kernel<<<o_grid, 256, GEMM_SMEM>>>(
        chi, clo, woh, wol, woh, wol, woh, wol,
        out, bo, nullptr, nullptr, nullptr, nullptr, nullptr, nullptr);
}